// round 4
// baseline (speedup 1.0000x reference)
#include <cuda_runtime.h>
#include <cuda_bf16.h>
#include <math.h>

// ArcFace-style margin softmax cross-entropy loss (fused single kernel).
//   loss = mean_b [ logsumexp_c(logits[b,c]) - logits[b, label_b] ]
// logits = clip(cos,-1+eps,1-eps)*64; label column replaced by
// (ct*cos(m) - sqrt(1-ct^2)*sin(m))*64.
//
// Single pass, fixed-shift logsumexp (shift = 64 = max possible logit).
// Final mean fused via threadfence + atomic-counter last-block pattern
// (counter resets itself -> graph-replay safe, no second launch).

#define EPS_CLIP 1e-7f
#define SCALE 64.0f
#define TPB 512

static __device__ float g_row_loss[4096];          // per-row losses (B <= 4096)
static __device__ unsigned int g_done_count = 0;   // reset to 0 by last block

__device__ __forceinline__ float clipf(float x) {
    return fminf(fmaxf(x, -1.0f + EPS_CLIP), 1.0f - EPS_CLIP);
}

// exp(logit - 64) where logit = clip(x)*64
__device__ __forceinline__ float term(float x) {
    return __expf(fmaf(clipf(x), SCALE, -SCALE));
}

__global__ void __launch_bounds__(TPB) margin_loss_fused_kernel(
    const float* __restrict__ cos_theta,
    const int* __restrict__ labels,
    const float* __restrict__ margins,
    float* __restrict__ out,
    int B, int C)
{
    const int row = blockIdx.x;
    const int tid = threadIdx.x;
    const size_t row_off = (size_t)row * (size_t)C;
    const float4* rp = reinterpret_cast<const float4*>(cos_theta + row_off);
    const int n4 = C >> 2;

    // 4 independent accumulators, 4x unrolled strided float4 loop:
    // 16 outstanding loads per thread before any dependency (high MLP).
    float a0 = 0.0f, a1 = 0.0f, a2 = 0.0f, a3 = 0.0f;
    int i = tid;
    const int step = TPB;
    const int bound4 = n4 - 3 * step;
    for (; i < bound4; i += 4 * step) {
        float4 v0 = __ldcs(rp + i);
        float4 v1 = __ldcs(rp + i + step);
        float4 v2 = __ldcs(rp + i + 2 * step);
        float4 v3 = __ldcs(rp + i + 3 * step);
        a0 += term(v0.x) + term(v0.y) + term(v0.z) + term(v0.w);
        a1 += term(v1.x) + term(v1.y) + term(v1.z) + term(v1.w);
        a2 += term(v2.x) + term(v2.y) + term(v2.z) + term(v2.w);
        a3 += term(v3.x) + term(v3.y) + term(v3.z) + term(v3.w);
    }
    for (; i < n4; i += step) {
        float4 v = __ldcs(rp + i);
        a0 += term(v.x) + term(v.y) + term(v.z) + term(v.w);
    }
    // scalar tail (C % 4)
    for (int j = (n4 << 2) + tid; j < C; j += step) {
        a0 += term(__ldcs(cos_theta + row_off + j));
    }
    float acc = (a0 + a1) + (a2 + a3);

    __shared__ float sdata[TPB];
    sdata[tid] = acc;
    __syncthreads();
    #pragma unroll
    for (int s = TPB / 2; s > 0; s >>= 1) {
        if (tid < s) sdata[tid] += sdata[tid + s];
        __syncthreads();
    }

    __shared__ bool s_is_last;
    if (tid == 0) {
        int lab = labels[row];
        float cl = clipf(cos_theta[row_off + (size_t)lab]);
        float m = margins[lab];
        float cm = cosf(m);
        float sm = sinf(m);
        float sin_l = sqrtf(fmaxf(1.0f - cl * cl, 0.0f));
        float target_logit = (cl * cm - sin_l * sm) * SCALE;

        // swap label-column contribution in the sum
        float sum = sdata[0]
                  + __expf(target_logit - SCALE)
                  - __expf(fmaf(cl, SCALE, -SCALE));

        g_row_loss[row] = (SCALE + logf(sum)) - target_logit;

        __threadfence();
        unsigned int prev = atomicAdd(&g_done_count, 1u);
        s_is_last = (prev == (unsigned int)(gridDim.x - 1));
    }
    __syncthreads();

    if (s_is_last) {
        // last block: deterministic tree reduction over all row losses
        float r = 0.0f;
        for (int j = tid; j < B; j += TPB) r += g_row_loss[j];
        sdata[tid] = r;
        __syncthreads();
        #pragma unroll
        for (int s = TPB / 2; s > 0; s >>= 1) {
            if (tid < s) sdata[tid] += sdata[tid + s];
            __syncthreads();
        }
        if (tid == 0) {
            out[0] = sdata[0] / (float)B;
            g_done_count = 0;   // reset for next graph replay
        }
    }
}

extern "C" void kernel_launch(void* const* d_in, const int* in_sizes, int n_in,
                              void* d_out, int out_size)
{
    const float* cos_theta = (const float*)d_in[0];
    const int*   labels    = (const int*)d_in[1];
    const float* margins   = (const float*)d_in[2];
    float* out = (float*)d_out;

    const int B = in_sizes[1];
    const int C = in_sizes[0] / B;

    margin_loss_fused_kernel<<<B, TPB>>>(cos_theta, labels, margins, out, B, C);
}

// round 5
// speedup vs baseline: 1.0292x; 1.0292x over previous
#include <cuda_runtime.h>
#include <cuda_bf16.h>
#include <math.h>

// ArcFace-style margin softmax cross-entropy loss (fused single kernel).
//   loss = mean_b [ logsumexp_c(logits[b,c]) - logits[b, label_b] ]
// logits = clip(cos,-1+eps,1-eps)*64; label column replaced by
// (ct*cos(m) - sqrt(1-ct^2)*sin(m))*64.
//
// Single pass, fixed-shift logsumexp (shift = 64 = max possible logit).
// Memory loop identical to the round-2 kernel that measured 6.33 TB/s
// (plain float4 loads, 256 threads, simple stride loop). Final mean fused
// via threadfence + self-resetting atomic counter (graph-replay safe).

#define EPS_CLIP 1e-7f
#define SCALE 64.0f
#define TPB 256

static __device__ float g_row_loss[4096];          // per-row losses (B <= 4096)
static __device__ unsigned int g_done_count = 0;   // reset to 0 by last block

__device__ __forceinline__ float clipf(float x) {
    return fminf(fmaxf(x, -1.0f + EPS_CLIP), 1.0f - EPS_CLIP);
}

// exp(logit - 64) where logit = clip(x)*64
__device__ __forceinline__ float term(float x) {
    return __expf(fmaf(clipf(x), SCALE, -SCALE));
}

__global__ void __launch_bounds__(TPB) margin_loss_fused_kernel(
    const float* __restrict__ cos_theta,
    const int* __restrict__ labels,
    const float* __restrict__ margins,
    float* __restrict__ out,
    int B, int C)
{
    const int row = blockIdx.x;
    const int tid = threadIdx.x;
    const size_t row_off = (size_t)row * (size_t)C;
    const float4* rp = reinterpret_cast<const float4*>(cos_theta + row_off);
    const int n4 = C >> 2;

    float acc = 0.0f;
    // strided float4 loads; fixed per-thread order -> deterministic.
    // (This exact loop shape measured 6.33 TB/s in round 2.)
    for (int i = tid; i < n4; i += TPB) {
        float4 v = rp[i];
        acc += term(v.x);
        acc += term(v.y);
        acc += term(v.z);
        acc += term(v.w);
    }
    // scalar tail (C % 4)
    for (int i = (n4 << 2) + tid; i < C; i += TPB) {
        acc += term(cos_theta[row_off + i]);
    }

    __shared__ float sdata[TPB];
    sdata[tid] = acc;
    __syncthreads();
    #pragma unroll
    for (int s = TPB / 2; s > 0; s >>= 1) {
        if (tid < s) sdata[tid] += sdata[tid + s];
        __syncthreads();
    }

    __shared__ bool s_is_last;
    if (tid == 0) {
        int lab = labels[row];
        float cl = clipf(cos_theta[row_off + (size_t)lab]);
        float m = margins[lab];
        float cm = cosf(m);
        float sm = sinf(m);
        float sin_l = sqrtf(fmaxf(1.0f - cl * cl, 0.0f));
        float target_logit = (cl * cm - sin_l * sm) * SCALE;

        // swap label-column contribution in the sum
        float sum = sdata[0]
                  + __expf(target_logit - SCALE)
                  - __expf(fmaf(cl, SCALE, -SCALE));

        g_row_loss[row] = (SCALE + logf(sum)) - target_logit;

        __threadfence();
        unsigned int prev = atomicAdd(&g_done_count, 1u);
        s_is_last = (prev == (unsigned int)(gridDim.x - 1));
    }
    __syncthreads();

    if (s_is_last) {
        // last block: deterministic tree reduction over all row losses
        float r = 0.0f;
        for (int j = tid; j < B; j += TPB) r += g_row_loss[j];
        sdata[tid] = r;
        __syncthreads();
        #pragma unroll
        for (int s = TPB / 2; s > 0; s >>= 1) {
            if (tid < s) sdata[tid] += sdata[tid + s];
            __syncthreads();
        }
        if (tid == 0) {
            out[0] = sdata[0] / (float)B;
            g_done_count = 0;   // reset for next graph replay
        }
    }
}

extern "C" void kernel_launch(void* const* d_in, const int* in_sizes, int n_in,
                              void* d_out, int out_size)
{
    const float* cos_theta = (const float*)d_in[0];
    const int*   labels    = (const int*)d_in[1];
    const float* margins   = (const float*)d_in[2];
    float* out = (float*)d_out;

    const int B = in_sizes[1];
    const int C = in_sizes[0] / B;

    margin_loss_fused_kernel<<<B, TPB>>>(cos_theta, labels, margins, out, B, C);
}